// round 6
// baseline (speedup 1.0000x reference)
#include <cuda_runtime.h>

#define PSZ 16
#define HW 224
#define NP 14          // patches per spatial dim (224/16)
#define S4 56          // float4 per strip row

__global__ __launch_bounds__(224) void patch_rotate_kernel(
    const float* __restrict__ x,
    const void* __restrict__ mask_raw,
    float* __restrict__ out)
{
    const int bid = blockIdx.x;
    const int hi  = bid % NP;              // patch-row index
    const int bc  = bid / NP;              // b*3 + c
    const int b   = bc / 3;
    const int t   = threadIdx.x;           // 0..223
    const int lane = t & 31;

    // thread -> (patch column, 4x4 sub-block): one patch per 16 consecutive lanes
    const int wi = t >> 4;                 // 0..13 patch column
    const int s  = t & 15;
    const int R  = s >> 2;                 // sub-block row (rows 4R..4R+3)
    const int J  = s & 3;                  // sub-block fcol within patch
    const int fcol = 4 * wi + J;

    const float4* src4 = (const float4*)(x   + (size_t)bc * (HW*HW) + (size_t)hi * (PSZ*HW));
    float4*       dst4 = (float4*)      (out + (size_t)bc * (HW*HW) + (size_t)hi * (PSZ*HW));

    // ---- issue all independent loads up front (x block, dtype probe, uint8 mask) ----
    float4 v[4];
    #pragma unroll
    for (int k = 0; k < 4; k++)
        v[k] = src4[(4*R + k) * S4 + fcol];

    // dtype probe: int32 bool buffer -> every word is 0/1; uint8 bool -> word>1 w.p. 7/8.
    // 32 words per warp: P(uint8 misdetected) = 8^-32.
    const unsigned pv = ((const unsigned int*)mask_raw)[lane];
    const int midx = b * (NP*NP) + wi * NP + hi;            // mask[b, wi, hi]
    const unsigned char m8 = ((const unsigned char*)mask_raw)[midx];  // in-bounds either way

    const bool is_int32 = (__ballot_sync(0xFFFFFFFFu, pv > 1u) == 0u);
    bool mm;
    if (is_int32) mm = (((const int*)mask_raw)[midx] != 0); // predicated: avoids OOB if uint8
    else          mm = (m8 != 0);

    // ---- transpose via half-warp lane exchange (only if any patch in warp is masked) ----
    float4 o[4];
    if (__ballot_sync(0xFFFFFFFFu, mm)) {
        const int src_lane = (lane & 16) | (J << 2) | R;    // mirror sub-block (J,R), same patch
        float4 g[4];
        #pragma unroll
        for (int e = 0; e < 4; e++) {
            g[e].x = __shfl_sync(0xFFFFFFFFu, v[e].x, src_lane);
            g[e].y = __shfl_sync(0xFFFFFFFFu, v[e].y, src_lane);
            g[e].z = __shfl_sync(0xFFFFFFFFu, v[e].z, src_lane);
            g[e].w = __shfl_sync(0xFFFFFFFFu, v[e].w, src_lane);
        }
        // 4x4 in-register transpose of the mirror block: o[k].e = g[e].k
        o[0] = make_float4(g[0].x, g[1].x, g[2].x, g[3].x);
        o[1] = make_float4(g[0].y, g[1].y, g[2].y, g[3].y);
        o[2] = make_float4(g[0].z, g[1].z, g[2].z, g[3].z);
        o[3] = make_float4(g[0].w, g[1].w, g[2].w, g[3].w);
        if (!mm) { o[0] = v[0]; o[1] = v[1]; o[2] = v[2]; o[3] = v[3]; }
    } else {
        o[0] = v[0]; o[1] = v[1]; o[2] = v[2]; o[3] = v[3];
    }

    // ---- coalesced stores (same 4x128B-line pattern as loads) ----
    #pragma unroll
    for (int k = 0; k < 4; k++)
        dst4[(4*R + k) * S4 + fcol] = o[k];
}

extern "C" void kernel_launch(void* const* d_in, const int* in_sizes, int n_in,
                              void* d_out, int out_size)
{
    const float* x    = (const float*)d_in[0];
    const void*  mask = d_in[1];
    float*       out  = (float*)d_out;

    // one block per (b, c, patch-row) strip = 256*3*14 = 10752 blocks
    patch_rotate_kernel<<<10752, 224>>>(x, mask, out);
}

// round 7
// speedup vs baseline: 1.0471x; 1.0471x over previous
#include <cuda_runtime.h>

#define PSZ 16
#define HW 224
#define NP 14          // patches per spatial dim (224/16)
#define S4 56          // float4 per strip row
#define PROWS 5        // padded smem row stride per patch (float4 units)
#define PSTRIDE 80     // per-patch smem size: 16 rows * 5 (float4)

__global__ __launch_bounds__(224) void patch_rotate_kernel(
    const float* __restrict__ x,
    const void* __restrict__ mask_raw,
    float* __restrict__ out)
{
    // per-warp private regions: 7 warps x 2 patches x 80 float4 = 17.5 KB
    __shared__ float4 tile[7 * 2 * PSTRIDE];

    const int bid = blockIdx.x;
    const int hi  = bid % NP;              // patch-row index
    const int bc  = bid / NP;              // b*3 + c
    const int b   = bc / 3;
    const int t   = threadIdx.x;           // 0..223
    const int lane = t & 31;

    // thread -> (patch, 4x4 sub-block): 16 consecutive lanes own one patch
    const int wi = t >> 4;                 // 0..13 patch column
    const int p  = (t >> 4) & 1;           // patch slot within warp
    const int R  = (t >> 2) & 3;           // sub-block row group (rows 4R..4R+3)
    const int J  = t & 3;                  // sub-block fcol within patch
    const int fcol = 4 * wi + J;

    float4* wtile = tile + (t >> 5) * (2 * PSTRIDE);   // this warp's region

    const float4* src4 = (const float4*)(x   + (size_t)bc * (HW*HW) + (size_t)hi * (PSZ*HW));
    float4*       dst4 = (float4*)      (out + (size_t)bc * (HW*HW) + (size_t)hi * (PSZ*HW));

    // ---- issue all independent loads up front ----
    float4 v[4];
    #pragma unroll
    for (int k = 0; k < 4; k++)
        v[k] = src4[(4*R + k) * S4 + fcol];

    // dtype probe: int32 bool buffer -> every word is 0/1; uint8 -> word>1 w.p. 7/8.
    // 32 words/warp: P(uint8 misdetected) = 8^-32.
    const unsigned pv = ((const unsigned int*)mask_raw)[lane];
    const int midx = b * (NP*NP) + wi * NP + hi;                      // mask[b, wi, hi]
    const unsigned char m8 = ((const unsigned char*)mask_raw)[midx];  // in-bounds either way

    const bool is_int32 = (__ballot_sync(0xFFFFFFFFu, pv > 1u) == 0u);
    bool mm;
    if (is_int32) mm = (((const int*)mask_raw)[midx] != 0);  // predicated: no OOB if uint8
    else          mm = (m8 != 0);

    // ---- register 4x4 transpose + vector STS (masked patches only, warp-local) ----
    // swizzled per-patch layout: phys(row, fc) = row*5 + (fc ^ ((row>>2)&2))
    if (mm) {
        const int jbit = (J & 2);
        #pragma unroll
        for (int e = 0; e < 4; e++) {
            int row = 4*J + e;                         // logical transposed row
            int adr = p * PSTRIDE + row * PROWS + (R ^ jbit);
            // column e of this thread's 4x4 block -> transposed row
            float4 w;
            w.x = (&v[0].x)[e]; w.y = (&v[1].x)[e]; w.z = (&v[2].x)[e]; w.w = (&v[3].x)[e];
            wtile[adr] = w;
        }
    }
    __syncwarp();

    // ---- gather + store: masked -> swizzled LDS.128, unmasked -> register passthrough ----
    const int rbit = (R & 2);
    #pragma unroll
    for (int k = 0; k < 4; k++) {
        float4 o = v[k];
        if (mm) {
            int row = 4*R + k;
            o = wtile[p * PSTRIDE + row * PROWS + (J ^ rbit)];
        }
        dst4[(4*R + k) * S4 + fcol] = o;
    }
}

extern "C" void kernel_launch(void* const* d_in, const int* in_sizes, int n_in,
                              void* d_out, int out_size)
{
    const float* x    = (const float*)d_in[0];
    const void*  mask = d_in[1];
    float*       out  = (float*)d_out;

    // one block per (b, c, patch-row) strip = 256*3*14 = 10752 blocks
    patch_rotate_kernel<<<10752, 224>>>(x, mask, out);
}